// round 13
// baseline (speedup 1.0000x reference)
#include <cuda_runtime.h>
#include <math.h>

#define T_LEN 512
#define B_SZ  64
#define D_SZ  1024
#define H_SZ  512
#define L_SZ  5

#define NCTA 128
#define NTHR 256      // proj kernel
#define NTSEQ 512     // sequential kernel

// ---------------- device-global scratch ----------------------------------------
__device__ float    g_XHt[T_LEN * H_SZ * B_SZ];     // [t][j][b]
__device__ float    g_XCt[T_LEN * H_SZ * B_SZ];     // [t][j][b]
__device__ float    g_hr[4][4][128][64];            // h ring [par][copy kg][row][b]
__device__ float    g_pr[2][2][4][H_SZ][B_SZ];      // partials [par][gate][kg][j][b]
__device__ unsigned g_fA[NCTA];                     // phase-A done flags (monotonic)
__device__ unsigned g_fB[NCTA];                     // h-contribution flags (monotonic)

// zero h(0) (ring slot 0) each launch; kernel boundary gives visibility
__global__ void init_kernel() {
    int idx = blockIdx.x * 256 + threadIdx.x;       // 32 blocks x 256 = 8192 float4
    ((float4*)&g_hr[0][0][0][0])[idx] = make_float4(0.f, 0.f, 0.f, 0.f);
}

// ---------------- precompute: XHt/XCt[t][j][b] = x[t,b,:]@W[:,j] + bias[j] ------
__global__ void __launch_bounds__(NTHR) proj_kernel(
    const float* __restrict__ x,
    const float* __restrict__ Ww,
    const float* __restrict__ Wb,
    const int gate)
{
    __shared__ float As[32][128];
    __shared__ float Bs[32][64];
    float* __restrict__ dst = gate ? g_XCt : g_XHt;

    const int tid = threadIdx.x;
    const int bm  = blockIdx.x * 128;
    const int bn  = blockIdx.y * 64;
    const int tm  = tid & 15;
    const int tn  = tid >> 4;

    float acc[8][4];
#pragma unroll
    for (int i = 0; i < 8; i++)
#pragma unroll
        for (int j = 0; j < 4; j++) acc[i][j] = 0.0f;

    for (int k0 = 0; k0 < D_SZ; k0 += 32) {
#pragma unroll
        for (int r = 0; r < 4; r++) {
            int lin = tid + r * 256;
            int m = lin >> 3, kq = lin & 7;
            float4 v = *(const float4*)(x + (size_t)(bm + m) * D_SZ + k0 + kq * 4);
            As[kq * 4 + 0][m] = v.x;
            As[kq * 4 + 1][m] = v.y;
            As[kq * 4 + 2][m] = v.z;
            As[kq * 4 + 3][m] = v.w;
        }
#pragma unroll
        for (int r = 0; r < 2; r++) {
            int lin = tid + r * 256;
            int kk = lin >> 4, jq = lin & 15;
            *(float4*)&Bs[kk][jq * 4] =
                *(const float4*)(Ww + (size_t)(k0 + kk) * H_SZ + bn + jq * 4);
        }
        __syncthreads();
#pragma unroll
        for (int k = 0; k < 32; k++) {
            float4 a0 = *(const float4*)&As[k][tm * 4];
            float4 a1 = *(const float4*)&As[k][64 + tm * 4];
            float4 bv = *(const float4*)&Bs[k][tn * 4];
            float av[8] = {a0.x, a0.y, a0.z, a0.w, a1.x, a1.y, a1.z, a1.w};
            float bw[4] = {bv.x, bv.y, bv.z, bv.w};
#pragma unroll
            for (int i = 0; i < 8; i++)
#pragma unroll
                for (int j = 0; j < 4; j++)
                    acc[i][j] = fmaf(av[i], bw[j], acc[i][j]);
        }
        __syncthreads();
    }

#pragma unroll
    for (int i = 0; i < 8; i++) {
        int m = bm + ((i < 4) ? (tm * 4 + i) : (64 + tm * 4 + i - 4));
        int t = m >> 6, b = m & 63;
#pragma unroll
        for (int j = 0; j < 4; j++) {
            int jj = bn + tn * 4 + j;
            dst[(size_t)t * (H_SZ * B_SZ) + (size_t)jj * B_SZ + b] = acc[i][j] + Wb[jj];
        }
    }
}

// ---------------- persistent dataflow kernel: NO grid barriers, 512 threads -----
// CTA (jg,kg): jg = cta>>2 (32 groups of 16 j), kg = cta&3 (128-k quarter).
// Thread = 4b x 1j x 1 gate (4 accs); per-k = 1 LDS.128 + 1 scalar LDS + 4 FFMA.
// Protocol identical to R12 (proven): fB waits (warp0, 32 flags), partial
// publish fA, fA waits (4 flags), phase B on threads 0-255, fB publish.
__global__ void __launch_bounds__(NTSEQ, 1) rhn_seq_kernel(
    const float* __restrict__ RHw, const float* __restrict__ RHb,
    const float* __restrict__ RCw, const float* __restrict__ RCb,
    float* __restrict__ out)
{
    const int tid  = threadIdx.x;
    const int cta  = blockIdx.x;
    const int jg   = cta >> 2;
    const int kg   = cta & 3;
    const int j0   = jg * 16;
    const int k0   = kg * 128;
    const int lane = tid & 31;
    const int warp = tid >> 5;

    __shared__ float hs[32][64];      // [k][b] chunk of hidden
    __shared__ float rhs_s[32][16];   // [k][j] chunk of R_H
    __shared__ float rcs_s[32][16];   // [k][j] chunk of R_C

    // launch-base of the monotonic flags (all equal across CTAs at launch start)
    const unsigned baseA = *(volatile unsigned*)&g_fA[cta];
    const unsigned baseB = *(volatile unsigned*)&g_fB[cta];

    // phase-A compute mapping
    const int gate = tid >> 8;        // warp-uniform
    const int s    = tid & 255;
    const int jx   = s & 15;          // j within group
    const int byq  = s >> 4;          // b quad (4 consecutive b), 0..15

    // weight staging mapping: tid<256 -> rhs_s, tid>=256 -> rcs_s (one float2)
    const int w    = tid & 255;
    const int kk_r = w >> 3, jq_r = w & 7;

    // phase-B mapping (threads 0..255): this CTA owns 4 j-rows of its jg slice
    const int jB    = j0 + kg * 4 + (tid >> 6);   // global j (tid<256)
    const int bB    = tid & 63;
    const int c_own = jg >> 3;                    // h copy receiving our rows
    const int r_own = (j0 + kg * 4 + (tid >> 6)) - 128 * c_own;

    float hold = 0.0f;                            // h(n)[jB][bB], register-carried

    float bHr[L_SZ], bCr[L_SZ];
#pragma unroll
    for (int l = 0; l < L_SZ; l++) {
        bHr[l] = RHb[l * H_SZ + (jB & (H_SZ - 1))];
        bCr[l] = RCb[l * H_SZ + (jB & (H_SZ - 1))];
    }

    int n = 0;
    for (int pass = 0; pass < 2; pass++)
    for (int t = 0; t < T_LEN; t++)
#pragma unroll
    for (int l = 0; l < L_SZ; l++, n++) {
        const float* __restrict__ Rh = RHw + (size_t)l * H_SZ * H_SZ;
        const float* __restrict__ Rc = RCw + (size_t)l * H_SZ * H_SZ;
        const float* __restrict__ Rsel = (tid < 256) ? Rh : Rc;
        const int pp = n & 1;

        // ---- flag-independent prefetches first (hide under the wait) ----
        float2 rv = *(const float2*)(Rsel + (size_t)(k0 + kk_r) * H_SZ + j0 + 2 * jq_r);
        float xh = 0.0f, xc = 0.0f;
        if (l == 0 && tid < 256) {
            xh = __ldcg(&g_XHt[(size_t)t * (H_SZ * B_SZ) + (size_t)jB * B_SZ + bB]);
            xc = __ldcg(&g_XCt[(size_t)t * (H_SZ * B_SZ) + (size_t)jB * B_SZ + bB]);
        }

        // ---- wait: h(n) copy kg ready (32 producers, contiguous flags) ----
        if (warp == 0) {
            volatile unsigned* f = &g_fB[32 * kg + lane];
            const unsigned tgt = baseB + (unsigned)n;
            while ((int)(*f - tgt) < 0) { }
        }
        __syncthreads();

        const float* __restrict__ hp = &g_hr[n & 3][kg][0][0];   // 128x64
        float4 h0v = __ldcg((const float4*)hp + tid);

        float a0 = 0.f, a1 = 0.f, a2 = 0.f, a3 = 0.f;

        const float (*rsel)[16] = gate ? rcs_s : rhs_s;

#pragma unroll
        for (int c = 0; c < 4; c++) {
            __syncthreads();
            ((float4*)hs)[tid] = h0v;
            if (tid < 256) ((float2*)rhs_s)[w] = rv;
            else           ((float2*)rcs_s)[w] = rv;
            __syncthreads();
            if (c < 3) {
                const int off = (c + 1) * 32;
                h0v = __ldcg((const float4*)(hp + off * 64) + tid);
                rv  = *(const float2*)(Rsel + (size_t)(k0 + off + kk_r) * H_SZ
                                       + j0 + 2 * jq_r);
            }
#pragma unroll
            for (int kk = 0; kk < 32; kk++) {
                float r = rsel[kk][jx];
                float4 hv = *(const float4*)&hs[kk][byq * 4];
                a0 = fmaf(hv.x, r, a0);
                a1 = fmaf(hv.y, r, a1);
                a2 = fmaf(hv.z, r, a2);
                a3 = fmaf(hv.w, r, a3);
            }
        }
        __stcg((float4*)&g_pr[pp][gate][kg][j0 + jx][byq * 4],
               make_float4(a0, a1, a2, a3));
        __syncthreads();
        if (tid == 0) {
            __threadfence();
            atomicExch(&g_fA[cta], baseA + (unsigned)n + 1u);
        }

        // ---- wait: 4 kg-peers' partials ready ----
        if (warp == 0 && lane < 4) {
            volatile unsigned* f = &g_fA[jg * 4 + lane];
            const unsigned tgt = baseA + (unsigned)n + 1u;
            while ((int)(*f - tgt) < 0) { }
        }
        __syncthreads();

        // ---- phase B (threads 0..255): reduce + activations + combine ----
        if (tid < 256) {
            float sH = __ldcg(&g_pr[pp][0][0][jB][bB]) + __ldcg(&g_pr[pp][0][1][jB][bB])
                     + __ldcg(&g_pr[pp][0][2][jB][bB]) + __ldcg(&g_pr[pp][0][3][jB][bB]);
            float sC = __ldcg(&g_pr[pp][1][0][jB][bB]) + __ldcg(&g_pr[pp][1][1][jB][bB])
                     + __ldcg(&g_pr[pp][1][2][jB][bB]) + __ldcg(&g_pr[pp][1][3][jB][bB]);
            sH += bHr[l];
            sC += bCr[l];
            if (l == 0) { sH += xh; sC += xc; }
            float hl = 1.0f - 2.0f / (1.0f + __expf(2.0f * sH));   // tanh
            float tl = 1.0f / (1.0f + __expf(-sC));                // sigmoid
            float hn = fmaf(tl, hl - hold, hold);
            hold = hn;
            __stcg(&g_hr[(n + 1) & 3][c_own][r_own][bB], hn);
            if (l == L_SZ - 1) {
                size_t o = (size_t)t * (B_SZ * 2 * H_SZ) + (size_t)bB * (2 * H_SZ)
                         + (size_t)pass * H_SZ + jB;
                out[o] = hn;
                if (t == T_LEN - 1) {
                    out[(size_t)T_LEN * (B_SZ * 2 * H_SZ) + (size_t)bB * (2 * H_SZ)
                        + (size_t)pass * H_SZ + jB] = hn;
                }
            }
        }
        __syncthreads();
        if (tid == 0) {
            __threadfence();
            atomicExch(&g_fB[cta], baseB + (unsigned)n + 1u);
        }
    }
}

extern "C" void kernel_launch(void* const* d_in, const int* in_sizes, int n_in,
                              void* d_out, int out_size)
{
    const float* x   = (const float*)d_in[0];
    const float* WHw = (const float*)d_in[1];
    const float* WHb = (const float*)d_in[2];
    const float* WCw = (const float*)d_in[3];
    const float* WCb = (const float*)d_in[4];
    const float* RHw = (const float*)d_in[5];
    const float* RHb = (const float*)d_in[6];
    const float* RCw = (const float*)d_in[7];
    const float* RCb = (const float*)d_in[8];
    float* out = (float*)d_out;

    init_kernel<<<32, 256>>>();
    dim3 pg(256, 8);
    proj_kernel<<<pg, NTHR>>>(x, WHw, WHb, 0);
    proj_kernel<<<pg, NTHR>>>(x, WCw, WCb, 1);
    rhn_seq_kernel<<<NCTA, NTSEQ>>>(RHw, RHb, RCw, RCb, out);
}

// round 14
// speedup vs baseline: 1.0011x; 1.0011x over previous
#include <cuda_runtime.h>
#include <math.h>

#define T_LEN 512
#define B_SZ  64
#define D_SZ  1024
#define H_SZ  512
#define L_SZ  5

#define NCTA 128
#define NTHR 256

typedef unsigned long long ull;

// ---------------- device-global scratch ----------------------------------------
__device__ float    g_XHt[T_LEN * H_SZ * B_SZ];     // [t][j][b]
__device__ float    g_XCt[T_LEN * H_SZ * B_SZ];     // [t][j][b]
__device__ float    g_hr[4][4][128][64];            // h ring [par][copy kg][row][b]
__device__ float    g_pr[2][2][4][H_SZ][B_SZ];      // partials [par][gate][kg][j][b]
__device__ unsigned g_fA[NCTA];                     // phase-A done flags (monotonic)
__device__ unsigned g_fB[NCTA];                     // h-contribution flags (monotonic)

// zero h(0) (ring slot 0) each launch; kernel boundary gives visibility
__global__ void init_kernel() {
    int idx = blockIdx.x * 256 + threadIdx.x;       // 32 blocks x 256 = 8192 float4
    ((float4*)&g_hr[0][0][0][0])[idx] = make_float4(0.f, 0.f, 0.f, 0.f);
}

// packed fp32x2 FMA (per-lane IEEE fp32)
__device__ __forceinline__ ull fma2(ull a, ull b, ull c) {
    ull d;
    asm("fma.rn.f32x2 %0, %1, %2, %3;" : "=l"(d) : "l"(a), "l"(b), "l"(c));
    return d;
}

// ---------------- precompute: XHt/XCt[t][j][b] = x[t,b,:]@W[:,j] + bias[j] ------
__global__ void __launch_bounds__(NTHR) proj_kernel(
    const float* __restrict__ x,
    const float* __restrict__ Ww,
    const float* __restrict__ Wb,
    const int gate)
{
    __shared__ float As[32][128];
    __shared__ float Bs[32][64];
    float* __restrict__ dst = gate ? g_XCt : g_XHt;

    const int tid = threadIdx.x;
    const int bm  = blockIdx.x * 128;
    const int bn  = blockIdx.y * 64;
    const int tm  = tid & 15;
    const int tn  = tid >> 4;

    float acc[8][4];
#pragma unroll
    for (int i = 0; i < 8; i++)
#pragma unroll
        for (int j = 0; j < 4; j++) acc[i][j] = 0.0f;

    for (int k0 = 0; k0 < D_SZ; k0 += 32) {
#pragma unroll
        for (int r = 0; r < 4; r++) {
            int lin = tid + r * 256;
            int m = lin >> 3, kq = lin & 7;
            float4 v = *(const float4*)(x + (size_t)(bm + m) * D_SZ + k0 + kq * 4);
            As[kq * 4 + 0][m] = v.x;
            As[kq * 4 + 1][m] = v.y;
            As[kq * 4 + 2][m] = v.z;
            As[kq * 4 + 3][m] = v.w;
        }
#pragma unroll
        for (int r = 0; r < 2; r++) {
            int lin = tid + r * 256;
            int kk = lin >> 4, jq = lin & 15;
            *(float4*)&Bs[kk][jq * 4] =
                *(const float4*)(Ww + (size_t)(k0 + kk) * H_SZ + bn + jq * 4);
        }
        __syncthreads();
#pragma unroll
        for (int k = 0; k < 32; k++) {
            float4 a0 = *(const float4*)&As[k][tm * 4];
            float4 a1 = *(const float4*)&As[k][64 + tm * 4];
            float4 bv = *(const float4*)&Bs[k][tn * 4];
            float av[8] = {a0.x, a0.y, a0.z, a0.w, a1.x, a1.y, a1.z, a1.w};
            float bw[4] = {bv.x, bv.y, bv.z, bv.w};
#pragma unroll
            for (int i = 0; i < 8; i++)
#pragma unroll
                for (int j = 0; j < 4; j++)
                    acc[i][j] = fmaf(av[i], bw[j], acc[i][j]);
        }
        __syncthreads();
    }

#pragma unroll
    for (int i = 0; i < 8; i++) {
        int m = bm + ((i < 4) ? (tm * 4 + i) : (64 + tm * 4 + i - 4));
        int t = m >> 6, b = m & 63;
#pragma unroll
        for (int j = 0; j < 4; j++) {
            int jj = bn + tn * 4 + j;
            dst[(size_t)t * (H_SZ * B_SZ) + (size_t)jj * B_SZ + b] = acc[i][j] + Wb[jj];
        }
    }
}

// ---------------- persistent dataflow kernel (R12 skeleton + fma.f32x2) ---------
// CTA (jg,kg): jg = cta>>2 (32 groups of 16 j), kg = cta&3 (128-k quarter).
// Thread = 1j x 4b (2 ull pairs) x 2 gates: per-kk = 1 LDS.128 + 2 LDS.64 +
// 4 FFMA2 => FMA2-pipe bound at 16 cyc/kk/SMSP (2048 cyc/layer floor).
// Weights pre-duplicated {r,r} in smem. Protocol identical to R12 (proven).
__global__ void __launch_bounds__(NTHR, 1) rhn_seq_kernel(
    const float* __restrict__ RHw, const float* __restrict__ RHb,
    const float* __restrict__ RCw, const float* __restrict__ RCb,
    float* __restrict__ out)
{
    const int tid  = threadIdx.x;
    const int cta  = blockIdx.x;
    const int jg   = cta >> 2;
    const int kg   = cta & 3;
    const int j0   = jg * 16;
    const int k0   = kg * 128;
    const int lane = tid & 31;
    const int warp = tid >> 5;

    __shared__ __align__(16) float  hs[32][64];      // [k][b] chunk of hidden
    __shared__ __align__(16) float2 rhd[32][16];     // [k][j] dup {r,r} R_H
    __shared__ __align__(16) float2 rcd[32][16];     // [k][j] dup {r,r} R_C

    // launch-base of the monotonic flags (all equal across CTAs at launch start)
    const unsigned baseA = *(volatile unsigned*)&g_fA[cta];
    const unsigned baseB = *(volatile unsigned*)&g_fB[cta];

    // phase-A mappings
    const int jx  = tid & 15;         // j within 16-wide group
    const int byq = tid >> 4;         // b quad (4 consecutive b)
    const int kk_r = tid >> 3, jq_r = tid & 7;

    // phase-B mapping: this CTA owns 4 j-rows of its jg slice
    const int jB    = j0 + kg * 4 + (tid >> 6);   // global j
    const int bB    = tid & 63;
    const int c_own = jg >> 3;                    // h copy receiving our rows
    const int r_own = jB - 128 * c_own;

    float hold = 0.0f;                            // h(n)[jB][bB], register-carried

    float bHr[L_SZ], bCr[L_SZ];
#pragma unroll
    for (int l = 0; l < L_SZ; l++) {
        bHr[l] = RHb[l * H_SZ + jB];
        bCr[l] = RCb[l * H_SZ + jB];
    }

    int n = 0;
    for (int pass = 0; pass < 2; pass++)
    for (int t = 0; t < T_LEN; t++)
#pragma unroll
    for (int l = 0; l < L_SZ; l++, n++) {
        const float* __restrict__ Rh = RHw + (size_t)l * H_SZ * H_SZ;
        const float* __restrict__ Rc = RCw + (size_t)l * H_SZ * H_SZ;
        const int pp = n & 1;

        // flag-independent prefetches (hide under the wait)
        float2 r0v = *(const float2*)(Rh + (size_t)(k0 + kk_r) * H_SZ + j0 + 2 * jq_r);
        float2 r1v = *(const float2*)(Rc + (size_t)(k0 + kk_r) * H_SZ + j0 + 2 * jq_r);
        float xh = 0.0f, xc = 0.0f;
        if (l == 0) {
            xh = __ldcg(&g_XHt[(size_t)t * (H_SZ * B_SZ) + (size_t)jB * B_SZ + bB]);
            xc = __ldcg(&g_XCt[(size_t)t * (H_SZ * B_SZ) + (size_t)jB * B_SZ + bB]);
        }

        // ---- wait: h(n) copy kg ready (32 producers, contiguous flags) ----
        if (warp == 0) {
            volatile unsigned* f = &g_fB[32 * kg + lane];
            const unsigned tgt = baseB + (unsigned)n;
            while ((int)(*f - tgt) < 0) { }
        }
        __syncthreads();

        const float* __restrict__ hp = &g_hr[n & 3][kg][0][0];   // 128x64

        ull aH0 = 0ull, aH1 = 0ull, aC0 = 0ull, aC1 = 0ull;

        float4 h0v = __ldcg((const float4*)hp + tid);
        float4 h1v = __ldcg((const float4*)hp + tid + 256);

#pragma unroll
        for (int c = 0; c < 4; c++) {
            __syncthreads();
            ((float4*)hs)[tid]       = h0v;
            ((float4*)hs)[tid + 256] = h1v;
            *(float4*)&rhd[kk_r][jq_r * 2] = make_float4(r0v.x, r0v.x, r0v.y, r0v.y);
            *(float4*)&rcd[kk_r][jq_r * 2] = make_float4(r1v.x, r1v.x, r1v.y, r1v.y);
            __syncthreads();
            if (c < 3) {
                const int off = (c + 1) * 32;
                h0v = __ldcg((const float4*)(hp + off * 64) + tid);
                h1v = __ldcg((const float4*)(hp + off * 64) + tid + 256);
                r0v = *(const float2*)(Rh + (size_t)(k0 + off + kk_r) * H_SZ + j0 + 2 * jq_r);
                r1v = *(const float2*)(Rc + (size_t)(k0 + off + kk_r) * H_SZ + j0 + 2 * jq_r);
            }
#pragma unroll
            for (int kk = 0; kk < 32; kk++) {
                const ulonglong2 hv = *(const ulonglong2*)&hs[kk][byq * 4];
                const ull rh = *(const ull*)&rhd[kk][jx];
                const ull rc = *(const ull*)&rcd[kk][jx];
                aH0 = fma2(hv.x, rh, aH0);   // b0b1, gate H
                aH1 = fma2(hv.y, rh, aH1);   // b2b3, gate H
                aC0 = fma2(hv.x, rc, aC0);   // b0b1, gate C
                aC1 = fma2(hv.y, rc, aC1);   // b2b3, gate C
            }
        }
        {
            float2 h01 = *(float2*)&aH0, h23 = *(float2*)&aH1;
            float2 c01 = *(float2*)&aC0, c23 = *(float2*)&aC1;
            __stcg((float4*)&g_pr[pp][0][kg][j0 + jx][byq * 4],
                   make_float4(h01.x, h01.y, h23.x, h23.y));
            __stcg((float4*)&g_pr[pp][1][kg][j0 + jx][byq * 4],
                   make_float4(c01.x, c01.y, c23.x, c23.y));
        }
        __syncthreads();
        if (tid == 0) {
            __threadfence();
            atomicExch(&g_fA[cta], baseA + (unsigned)n + 1u);
        }

        // ---- wait: 4 kg-peers' partials ready ----
        if (warp == 0 && lane < 4) {
            volatile unsigned* f = &g_fA[jg * 4 + lane];
            const unsigned tgt = baseA + (unsigned)n + 1u;
            while ((int)(*f - tgt) < 0) { }
        }
        __syncthreads();

        // ---- phase B: reduce + activations + highway combine ----
        {
            float sH = __ldcg(&g_pr[pp][0][0][jB][bB]) + __ldcg(&g_pr[pp][0][1][jB][bB])
                     + __ldcg(&g_pr[pp][0][2][jB][bB]) + __ldcg(&g_pr[pp][0][3][jB][bB]);
            float sC = __ldcg(&g_pr[pp][1][0][jB][bB]) + __ldcg(&g_pr[pp][1][1][jB][bB])
                     + __ldcg(&g_pr[pp][1][2][jB][bB]) + __ldcg(&g_pr[pp][1][3][jB][bB]);
            sH += bHr[l];
            sC += bCr[l];
            if (l == 0) { sH += xh; sC += xc; }
            float hl = 1.0f - 2.0f / (1.0f + __expf(2.0f * sH));   // tanh
            float tl = 1.0f / (1.0f + __expf(-sC));                // sigmoid
            float hn = fmaf(tl, hl - hold, hold);
            hold = hn;
            __stcg(&g_hr[(n + 1) & 3][c_own][r_own][bB], hn);
            if (l == L_SZ - 1) {
                size_t o = (size_t)t * (B_SZ * 2 * H_SZ) + (size_t)bB * (2 * H_SZ)
                         + (size_t)pass * H_SZ + jB;
                out[o] = hn;
                if (t == T_LEN - 1) {
                    out[(size_t)T_LEN * (B_SZ * 2 * H_SZ) + (size_t)bB * (2 * H_SZ)
                        + (size_t)pass * H_SZ + jB] = hn;
                }
            }
        }
        __syncthreads();
        if (tid == 0) {
            __threadfence();
            atomicExch(&g_fB[cta], baseB + (unsigned)n + 1u);
        }
    }
}

extern "C" void kernel_launch(void* const* d_in, const int* in_sizes, int n_in,
                              void* d_out, int out_size)
{
    const float* x   = (const float*)d_in[0];
    const float* WHw = (const float*)d_in[1];
    const float* WHb = (const float*)d_in[2];
    const float* WCw = (const float*)d_in[3];
    const float* WCb = (const float*)d_in[4];
    const float* RHw = (const float*)d_in[5];
    const float* RHb = (const float*)d_in[6];
    const float* RCw = (const float*)d_in[7];
    const float* RCb = (const float*)d_in[8];
    float* out = (float*)d_out;

    init_kernel<<<32, 256>>>();
    dim3 pg(256, 8);
    proj_kernel<<<pg, NTHR>>>(x, WHw, WHb, 0);
    proj_kernel<<<pg, NTHR>>>(x, WCw, WCb, 1);
    rhn_seq_kernel<<<NCTA, NTHR>>>(RHw, RHb, RCw, RCb, out);
}

// round 15
// speedup vs baseline: 1.1926x; 1.1913x over previous
#include <cuda_runtime.h>
#include <math.h>

#define T_LEN 512
#define B_SZ  64
#define D_SZ  1024
#define H_SZ  512
#define L_SZ  5

#define NCTA 128
#define NTHR 256

// dynamic smem layout (floats): hs[128][64] | rhs[128][16] | rcs[128][16]
#define SM_HS  0
#define SM_RH  (128 * 64)
#define SM_RC  (SM_RH + 128 * 16)
#define SM_TOT ((SM_RC + 128 * 16) * 4)   // 49152 bytes

// ---------------- device-global scratch ----------------------------------------
__device__ float    g_XHt[T_LEN * H_SZ * B_SZ];     // [t][j][b]
__device__ float    g_XCt[T_LEN * H_SZ * B_SZ];     // [t][j][b]
__device__ float    g_hr[4][4][128][64];            // h ring [par][copy kg][row][b]
__device__ float    g_pr[2][2][4][H_SZ][B_SZ];      // partials [par][gate][kg][j][b]
__device__ unsigned g_fA[NCTA];                     // phase-A done flags (monotonic)
__device__ unsigned g_fB[NCTA];                     // h-contribution flags (monotonic)

// zero h(0) (ring slot 0) each launch; kernel boundary gives visibility
__global__ void init_kernel() {
    int idx = blockIdx.x * 256 + threadIdx.x;       // 32 blocks x 256 = 8192 float4
    ((float4*)&g_hr[0][0][0][0])[idx] = make_float4(0.f, 0.f, 0.f, 0.f);
}

// ---------------- precompute: XHt/XCt[t][j][b] = x[t,b,:]@W[:,j] + bias[j] ------
__global__ void __launch_bounds__(NTHR) proj_kernel(
    const float* __restrict__ x,
    const float* __restrict__ Ww,
    const float* __restrict__ Wb,
    const int gate)
{
    __shared__ float As[32][128];
    __shared__ float Bs[32][64];
    float* __restrict__ dst = gate ? g_XCt : g_XHt;

    const int tid = threadIdx.x;
    const int bm  = blockIdx.x * 128;
    const int bn  = blockIdx.y * 64;
    const int tm  = tid & 15;
    const int tn  = tid >> 4;

    float acc[8][4];
#pragma unroll
    for (int i = 0; i < 8; i++)
#pragma unroll
        for (int j = 0; j < 4; j++) acc[i][j] = 0.0f;

    for (int k0 = 0; k0 < D_SZ; k0 += 32) {
#pragma unroll
        for (int r = 0; r < 4; r++) {
            int lin = tid + r * 256;
            int m = lin >> 3, kq = lin & 7;
            float4 v = *(const float4*)(x + (size_t)(bm + m) * D_SZ + k0 + kq * 4);
            As[kq * 4 + 0][m] = v.x;
            As[kq * 4 + 1][m] = v.y;
            As[kq * 4 + 2][m] = v.z;
            As[kq * 4 + 3][m] = v.w;
        }
#pragma unroll
        for (int r = 0; r < 2; r++) {
            int lin = tid + r * 256;
            int kk = lin >> 4, jq = lin & 15;
            *(float4*)&Bs[kk][jq * 4] =
                *(const float4*)(Ww + (size_t)(k0 + kk) * H_SZ + bn + jq * 4);
        }
        __syncthreads();
#pragma unroll
        for (int k = 0; k < 32; k++) {
            float4 a0 = *(const float4*)&As[k][tm * 4];
            float4 a1 = *(const float4*)&As[k][64 + tm * 4];
            float4 bv = *(const float4*)&Bs[k][tn * 4];
            float av[8] = {a0.x, a0.y, a0.z, a0.w, a1.x, a1.y, a1.z, a1.w};
            float bw[4] = {bv.x, bv.y, bv.z, bv.w};
#pragma unroll
            for (int i = 0; i < 8; i++)
#pragma unroll
                for (int j = 0; j < 4; j++)
                    acc[i][j] = fmaf(av[i], bw[j], acc[i][j]);
        }
        __syncthreads();
    }

#pragma unroll
    for (int i = 0; i < 8; i++) {
        int m = bm + ((i < 4) ? (tm * 4 + i) : (64 + tm * 4 + i - 4));
        int t = m >> 6, b = m & 63;
#pragma unroll
        for (int j = 0; j < 4; j++) {
            int jj = bn + tn * 4 + j;
            dst[(size_t)t * (H_SZ * B_SZ) + (size_t)jj * B_SZ + b] = acc[i][j] + Wb[jj];
        }
    }
}

// ---------------- persistent dataflow kernel (R12 protocol, restaged phase A) ---
// CTA (jg,kg): jg = cta>>2 (32 groups of 16 j), kg = cta&3 (128-k quarter).
// Per layer: [stage weights to smem — flag-independent, hidden under fB wait]
//   -> fB wait (warp0, 32 flags) -> stage all 128 h rows (MLP=8) -> ONE sync
//   -> 128-kk compute (pure LDS+FFMA) -> publish fA -> fA wait (4 flags)
//   -> phase B -> publish fB.
__global__ void __launch_bounds__(NTHR, 1) rhn_seq_kernel(
    const float* __restrict__ RHw, const float* __restrict__ RHb,
    const float* __restrict__ RCw, const float* __restrict__ RCb,
    float* __restrict__ out)
{
    extern __shared__ __align__(16) float smem[];
    float* __restrict__ hs  = smem + SM_HS;   // [128][64]
    float* __restrict__ rhs = smem + SM_RH;   // [128][16]
    float* __restrict__ rcs = smem + SM_RC;   // [128][16]

    const int tid  = threadIdx.x;
    const int cta  = blockIdx.x;
    const int jg   = cta >> 2;
    const int kg   = cta & 3;
    const int j0   = jg * 16;
    const int k0   = kg * 128;
    const int lane = tid & 31;
    const int warp = tid >> 5;

    // launch-base of the monotonic flags (all equal across CTAs at launch start)
    const unsigned baseA = *(volatile unsigned*)&g_fA[cta];
    const unsigned baseB = *(volatile unsigned*)&g_fB[cta];

    // phase-A mappings
    const int jx  = tid & 15;         // j within 16-wide group
    const int byq = tid >> 4;         // b quad (4 consecutive b)
    const int kk_r = tid >> 3, jq_r = tid & 7;   // weight staging: (k row, j pair)

    // phase-B mapping: this CTA owns 4 j-rows of its jg slice
    const int jB    = j0 + kg * 4 + (tid >> 6);   // global j
    const int bB    = tid & 63;
    const int c_own = jg >> 3;                    // h copy receiving our rows
    const int r_own = jB - 128 * c_own;

    float hold = 0.0f;                            // h(n)[jB][bB], register-carried

    float bHr[L_SZ], bCr[L_SZ];
#pragma unroll
    for (int l = 0; l < L_SZ; l++) {
        bHr[l] = RHb[l * H_SZ + jB];
        bCr[l] = RCb[l * H_SZ + jB];
    }

    int n = 0;
    for (int pass = 0; pass < 2; pass++)
    for (int t = 0; t < T_LEN; t++)
#pragma unroll
    for (int l = 0; l < L_SZ; l++, n++) {
        const float* __restrict__ Rh = RHw + (size_t)l * H_SZ * H_SZ;
        const float* __restrict__ Rc = RCw + (size_t)l * H_SZ * H_SZ;
        const int pp = n & 1;

        // ---- stage weights to smem NOW (flag-independent; hidden under wait) ----
        // thread covers 4 k-rows x 1 j-pair for each gate
#pragma unroll
        for (int i = 0; i < 4; i++) {
            const int kr = kk_r + 32 * i;
            float2 rh = *(const float2*)(Rh + (size_t)(k0 + kr) * H_SZ + j0 + 2 * jq_r);
            float2 rc = *(const float2*)(Rc + (size_t)(k0 + kr) * H_SZ + j0 + 2 * jq_r);
            *(float2*)&rhs[kr * 16 + 2 * jq_r] = rh;
            *(float2*)&rcs[kr * 16 + 2 * jq_r] = rc;
        }
        float xh = 0.0f, xc = 0.0f;
        if (l == 0) {
            xh = __ldcg(&g_XHt[(size_t)t * (H_SZ * B_SZ) + (size_t)jB * B_SZ + bB]);
            xc = __ldcg(&g_XCt[(size_t)t * (H_SZ * B_SZ) + (size_t)jB * B_SZ + bB]);
        }

        // ---- wait: h(n) copy kg ready (32 producers, contiguous flags) ----
        if (warp == 0) {
            volatile unsigned* f = &g_fB[32 * kg + lane];
            const unsigned tgt = baseB + (unsigned)n;
            while ((int)(*f - tgt) < 0) { }
        }
        __syncthreads();   // releases wait to all warps; also covers weight stores

        // ---- stage all 128 h rows with max MLP ----
        const float* __restrict__ hp = &g_hr[n & 3][kg][0][0];   // 128x64
        {
            float4 hv[8];
#pragma unroll
            for (int i = 0; i < 8; i++)
                hv[i] = __ldcg((const float4*)hp + tid + 256 * i);
#pragma unroll
            for (int i = 0; i < 8; i++)
                ((float4*)hs)[tid + 256 * i] = hv[i];
        }
        __syncthreads();

        // ---- compute: 128 kk, pure LDS + FFMA ----
        float aH0 = 0, aH1 = 0, aH2 = 0, aH3 = 0;
        float aC0 = 0, aC1 = 0, aC2 = 0, aC3 = 0;
#pragma unroll 16
        for (int kk = 0; kk < 128; kk++) {
            float rh = rhs[kk * 16 + jx];
            float rc = rcs[kk * 16 + jx];
            float4 hv = *(const float4*)&hs[kk * 64 + byq * 4];
            aH0 = fmaf(hv.x, rh, aH0); aH1 = fmaf(hv.y, rh, aH1);
            aH2 = fmaf(hv.z, rh, aH2); aH3 = fmaf(hv.w, rh, aH3);
            aC0 = fmaf(hv.x, rc, aC0); aC1 = fmaf(hv.y, rc, aC1);
            aC2 = fmaf(hv.z, rc, aC2); aC3 = fmaf(hv.w, rc, aC3);
        }
        __stcg((float4*)&g_pr[pp][0][kg][j0 + jx][byq * 4],
               make_float4(aH0, aH1, aH2, aH3));
        __stcg((float4*)&g_pr[pp][1][kg][j0 + jx][byq * 4],
               make_float4(aC0, aC1, aC2, aC3));
        __syncthreads();
        if (tid == 0) {
            __threadfence();
            atomicExch(&g_fA[cta], baseA + (unsigned)n + 1u);
        }

        // ---- wait: 4 kg-peers' partials ready ----
        if (warp == 0 && lane < 4) {
            volatile unsigned* f = &g_fA[jg * 4 + lane];
            const unsigned tgt = baseA + (unsigned)n + 1u;
            while ((int)(*f - tgt) < 0) { }
        }
        __syncthreads();

        // ---- phase B: reduce + activations + highway combine ----
        {
            float sH = __ldcg(&g_pr[pp][0][0][jB][bB]) + __ldcg(&g_pr[pp][0][1][jB][bB])
                     + __ldcg(&g_pr[pp][0][2][jB][bB]) + __ldcg(&g_pr[pp][0][3][jB][bB]);
            float sC = __ldcg(&g_pr[pp][1][0][jB][bB]) + __ldcg(&g_pr[pp][1][1][jB][bB])
                     + __ldcg(&g_pr[pp][1][2][jB][bB]) + __ldcg(&g_pr[pp][1][3][jB][bB]);
            sH += bHr[l];
            sC += bCr[l];
            if (l == 0) { sH += xh; sC += xc; }
            float hl = 1.0f - 2.0f / (1.0f + __expf(2.0f * sH));   // tanh
            float tl = 1.0f / (1.0f + __expf(-sC));                // sigmoid
            float hn = fmaf(tl, hl - hold, hold);
            hold = hn;
            __stcg(&g_hr[(n + 1) & 3][c_own][r_own][bB], hn);
            if (l == L_SZ - 1) {
                size_t o = (size_t)t * (B_SZ * 2 * H_SZ) + (size_t)bB * (2 * H_SZ)
                         + (size_t)pass * H_SZ + jB;
                out[o] = hn;
                if (t == T_LEN - 1) {
                    out[(size_t)T_LEN * (B_SZ * 2 * H_SZ) + (size_t)bB * (2 * H_SZ)
                        + (size_t)pass * H_SZ + jB] = hn;
                }
            }
        }
        __syncthreads();
        if (tid == 0) {
            __threadfence();
            atomicExch(&g_fB[cta], baseB + (unsigned)n + 1u);
        }
    }
}

extern "C" void kernel_launch(void* const* d_in, const int* in_sizes, int n_in,
                              void* d_out, int out_size)
{
    const float* x   = (const float*)d_in[0];
    const float* WHw = (const float*)d_in[1];
    const float* WHb = (const float*)d_in[2];
    const float* WCw = (const float*)d_in[3];
    const float* WCb = (const float*)d_in[4];
    const float* RHw = (const float*)d_in[5];
    const float* RHb = (const float*)d_in[6];
    const float* RCw = (const float*)d_in[7];
    const float* RCb = (const float*)d_in[8];
    float* out = (float*)d_out;

    cudaFuncSetAttribute(rhn_seq_kernel,
                         cudaFuncAttributeMaxDynamicSharedMemorySize, SM_TOT);

    init_kernel<<<32, 256>>>();
    dim3 pg(256, 8);
    proj_kernel<<<pg, NTHR>>>(x, WHw, WHb, 0);
    proj_kernel<<<pg, NTHR>>>(x, WCw, WCb, 1);
    rhn_seq_kernel<<<NCTA, NTHR, SM_TOT>>>(RHw, RHb, RCw, RCb, out);
}

// round 17
// speedup vs baseline: 1.6974x; 1.4233x over previous
#include <cuda_runtime.h>
#include <cuda_bf16.h>
#include <math.h>

#define T_LEN 512
#define B_SZ  64
#define D_SZ  1024
#define H_SZ  512
#define L_SZ  5

#define NCTA 128
#define NTHR 256

// seq smem layout (bytes): A tiles 16KB | B tiles 32KB = 48KB static
#define SA 0
#define SB 16384

typedef unsigned long long ull;

// ---------------- device-global scratch ----------------------------------------
__device__ float          g_XHt[T_LEN * H_SZ * B_SZ];   // [t][j][b]
__device__ float          g_XCt[T_LEN * H_SZ * B_SZ];   // [t][j][b]
__device__ __nv_bfloat16  g_hb[4][2][H_SZ][B_SZ];       // h ring [slot][term][j][b]
__device__ float          g_pr[2][2][4][H_SZ][B_SZ];    // [par][gate][kg][j][b]
__device__ __nv_bfloat16  g_Aw[5 * 2 * 2 * 32 * 4 * 2048]; // A tiles [l][g][term][jg][kg][16][128]
__device__ unsigned       g_fA[NCTA];
__device__ unsigned       g_fB[NCTA];

// ---------------- helpers -------------------------------------------------------
__device__ __forceinline__ unsigned smem_u32(const void* p) {
    unsigned a;
    asm("{ .reg .u64 t; cvta.to.shared.u64 t, %1; cvt.u32.u64 %0, t; }"
        : "=r"(a) : "l"(p));
    return a;
}
__device__ __forceinline__ void cpa16(unsigned sdst, const void* src) {
    asm volatile("cp.async.cg.shared.global [%0], [%1], 16;"
                 :: "r"(sdst), "l"(src) : "memory");
}
__device__ __forceinline__ void cpa_wait_all() {
    asm volatile("cp.async.wait_all;" ::: "memory");
}

// zero ring slot 0 (both terms): 2*512*64*2B = 128KB = 8192 uint4
__global__ void init_kernel() {
    int idx = blockIdx.x * 256 + threadIdx.x;
    ((uint4*)&g_hb[0][0][0][0])[idx] = make_uint4(0, 0, 0, 0);
}

// split R into bf16 hi/lo, transpose to A[m=j][k] tiles [l][g][term][jg][kg][16][128]
__global__ void split_kernel(const float* __restrict__ RHw,
                             const float* __restrict__ RCw) {
    int e = blockIdx.x * 256 + threadIdx.x;     // 5*2*512*512 = 2,621,440
    int j = e & 511;
    int k = (e >> 9) & 511;
    int g = (e >> 18) & 1;
    int l = e >> 19;
    float v = (g ? RCw : RHw)[(size_t)l * (H_SZ * H_SZ) + (size_t)k * H_SZ + j];
    __nv_bfloat16 hi = __float2bfloat16_rn(v);
    __nv_bfloat16 lo = __float2bfloat16_rn(v - __bfloat162float(hi));
    int jgs = j >> 4, jl = j & 15;
    int kgs = k >> 7, kl = k & 127;
    size_t base = ((((size_t)(l * 2 + g) * 2) * 32 + jgs) * 4 + kgs) * 2048
                + (size_t)jl * 128 + kl;
    g_Aw[base] = hi;                                  // term 0
    g_Aw[base + (size_t)32 * 4 * 2048] = lo;          // term 1
}

// ---------------- precompute: XHt/XCt[t][j][b] = x[t,b,:]@W[:,j] + bias[j] ------
__global__ void __launch_bounds__(NTHR) proj_kernel(
    const float* __restrict__ x,
    const float* __restrict__ Ww,
    const float* __restrict__ Wb,
    const int gate)
{
    __shared__ float As[32][128];
    __shared__ float Bs[32][64];
    float* __restrict__ dst = gate ? g_XCt : g_XHt;

    const int tid = threadIdx.x;
    const int bm  = blockIdx.x * 128;
    const int bn  = blockIdx.y * 64;
    const int tm  = tid & 15;
    const int tn  = tid >> 4;

    float acc[8][4];
#pragma unroll
    for (int i = 0; i < 8; i++)
#pragma unroll
        for (int j = 0; j < 4; j++) acc[i][j] = 0.0f;

    for (int k0 = 0; k0 < D_SZ; k0 += 32) {
#pragma unroll
        for (int r = 0; r < 4; r++) {
            int lin = tid + r * 256;
            int m = lin >> 3, kq = lin & 7;
            float4 v = *(const float4*)(x + (size_t)(bm + m) * D_SZ + k0 + kq * 4);
            As[kq * 4 + 0][m] = v.x;
            As[kq * 4 + 1][m] = v.y;
            As[kq * 4 + 2][m] = v.z;
            As[kq * 4 + 3][m] = v.w;
        }
#pragma unroll
        for (int r = 0; r < 2; r++) {
            int lin = tid + r * 256;
            int kk = lin >> 4, jq = lin & 15;
            *(float4*)&Bs[kk][jq * 4] =
                *(const float4*)(Ww + (size_t)(k0 + kk) * H_SZ + bn + jq * 4);
        }
        __syncthreads();
#pragma unroll
        for (int k = 0; k < 32; k++) {
            float4 a0 = *(const float4*)&As[k][tm * 4];
            float4 a1 = *(const float4*)&As[k][64 + tm * 4];
            float4 bv = *(const float4*)&Bs[k][tn * 4];
            float av[8] = {a0.x, a0.y, a0.z, a0.w, a1.x, a1.y, a1.z, a1.w};
            float bw[4] = {bv.x, bv.y, bv.z, bv.w};
#pragma unroll
            for (int i = 0; i < 8; i++)
#pragma unroll
                for (int j = 0; j < 4; j++)
                    acc[i][j] = fmaf(av[i], bw[j], acc[i][j]);
        }
        __syncthreads();
    }

#pragma unroll
    for (int i = 0; i < 8; i++) {
        int m = bm + ((i < 4) ? (tm * 4 + i) : (64 + tm * 4 + i - 4));
        int t = m >> 6, b = m & 63;
#pragma unroll
        for (int j = 0; j < 4; j++) {
            int jj = bn + tn * 4 + j;
            dst[(size_t)t * (H_SZ * B_SZ) + (size_t)jj * B_SZ + b] = acc[i][j] + Wb[jj];
        }
    }
}

// ---------------- persistent HMMA dataflow kernel (R15 protocol) ----------------
// CTA (jg = cta>>2, kg = cta&3): tile 16j x 64b x 128k x 2 gates, bf16 hi/lo
// 3-term mma.sync.m16n8k16. Warp w: gate = w>>2, n-tile pair = w&3.
__global__ void __launch_bounds__(NTHR, 1) rhn_seq_kernel(
    const float* __restrict__ RHb, const float* __restrict__ RCb,
    float* __restrict__ out)
{
    __shared__ __align__(1024) char smem[49152];
    const unsigned sb = smem_u32(smem);

    const int tid  = threadIdx.x;
    const int cta  = blockIdx.x;
    const int jg   = cta >> 2;
    const int kg   = cta & 3;
    const int lane = tid & 31;
    const int warp = tid >> 5;

    const unsigned baseA = *(volatile unsigned*)&g_fA[cta];
    const unsigned baseB = *(volatile unsigned*)&g_fB[cta];

    // warp compute mapping
    const int gate = warp >> 2;
    const int ntp  = warp & 3;
    const int r    = lane & 7;
    const int g    = lane >> 3;
    const int arow = r + 8 * (g & 1);
    const int ac   = g >> 1;                 // A k-chunk half
    const unsigned aBase = sb + SA + gate * 8192 + arow * 256;
    const int ntB = ntp * 2 + (g >> 1);
    const unsigned bBase = sb + SB + ((g & 1) * 8 + r) * 128
                         + (unsigned)((ntB ^ r) << 4);

    // phase-B mapping: 1 element/thread
    const int jB = jg * 16 + kg * 4 + (tid >> 6);
    const int bB = tid & 63;

    float hold = 0.0f;
    float bHr[L_SZ], bCr[L_SZ];
#pragma unroll
    for (int l = 0; l < L_SZ; l++) {
        bHr[l] = RHb[l * H_SZ + jB];
        bCr[l] = RCb[l * H_SZ + jB];
    }

    int n = 0;
    for (int pass = 0; pass < 2; pass++)
    for (int t = 0; t < T_LEN; t++)
#pragma unroll
    for (int l = 0; l < L_SZ; l++, n++) {
        const int pp = n & 1;
        const int ns = (n + 1) & 3;

        // ---- A-tile stage (flag-independent; hidden under fB wait) ----
        {
            const __nv_bfloat16* lt = g_Aw
                + ((((size_t)(l * 2) * 2) * 32) * 4) * 2048;  // l base
#pragma unroll
            for (int i = 0; i < 4; i++) {
                int lin = tid + i * 256;          // 0..1023
                int gt  = lin >> 8;               // gate*2+term
                int rem = lin & 255;
                int jA  = rem >> 4;
                int cA  = rem & 15;
                const char* src = (const char*)(g_Aw
                    + ((((size_t)(l * 2 + (gt >> 1)) * 2 + (gt & 1)) * 32 + jg) * 4 + kg) * 2048)
                    + jA * 256 + cA * 16;
                unsigned dst = sb + SA + gt * 4096 + jA * 256
                             + (unsigned)(((cA ^ (jA & 7))) << 4);
                cpa16(dst, src);
            }
            (void)lt;
        }
        float xh = 0.0f, xc = 0.0f;
        if (l == 0) {
            xh = __ldcg(&g_XHt[(size_t)t * (H_SZ * B_SZ) + (size_t)jB * B_SZ + bB]);
            xc = __ldcg(&g_XCt[(size_t)t * (H_SZ * B_SZ) + (size_t)jB * B_SZ + bB]);
        }

        // ---- wait: h(n) rows [128kg,+128) ready (producers 32kg..32kg+31) ----
        if (warp == 0) {
            volatile unsigned* f = &g_fB[32 * kg + lane];
            const unsigned tgt = baseB + (unsigned)n;
            while ((int)(*f - tgt) < 0) { }
        }
        __syncthreads();

        // ---- B-tile stage: ring bf16 [j][b], rows 128kg..+128, both terms ----
        {
            const int slot = n & 3;
#pragma unroll
            for (int i = 0; i < 8; i++) {
                int lin  = tid + i * 256;        // 0..2047
                int term = lin >> 10;
                int rem  = lin & 1023;
                int kB   = rem >> 3;             // 0..127
                int cB   = rem & 7;              // 16B chunk = n-tile index
                const void* src = &g_hb[slot][term][128 * kg + kB][cB * 8];
                unsigned dst = sb + SB + term * 16384 + kB * 128
                             + (unsigned)(((cB ^ (kB & 7))) << 4);
                cpa16(dst, src);
            }
        }
        cpa_wait_all();
        __syncthreads();

        // ---- compute: 3 terms x 8 k-steps, 2 mma each ----
        float acc[8];
#pragma unroll
        for (int i = 0; i < 8; i++) acc[i] = 0.0f;
#pragma unroll
        for (int term = 0; term < 3; term++) {
            const int at = (term == 2) ? 1 : 0;   // A lo on term 2
            const int bt = (term == 1) ? 1 : 0;   // B lo on term 1
            const unsigned aT = aBase + at * 4096;
            const unsigned bT = bBase + bt * 16384;
#pragma unroll
            for (int ks = 0; ks < 8; ks++) {
                unsigned aaddr = aT + (unsigned)((((ks << 1) + ac) ^ r) << 4);
                unsigned baddr = bT + ks * 2048;
                unsigned a0, a1, a2, a3, b0, b1, b2, b3;
                asm volatile(
                    "ldmatrix.sync.aligned.m8n8.x4.shared.b16 {%0,%1,%2,%3}, [%4];"
                    : "=r"(a0), "=r"(a1), "=r"(a2), "=r"(a3) : "r"(aaddr));
                asm volatile(
                    "ldmatrix.sync.aligned.m8n8.x4.trans.shared.b16 {%0,%1,%2,%3}, [%4];"
                    : "=r"(b0), "=r"(b1), "=r"(b2), "=r"(b3) : "r"(baddr));
                asm volatile(
                    "mma.sync.aligned.m16n8k16.row.col.f32.bf16.bf16.f32 "
                    "{%0,%1,%2,%3}, {%4,%5,%6,%7}, {%8,%9}, {%0,%1,%2,%3};"
                    : "+f"(acc[0]), "+f"(acc[1]), "+f"(acc[2]), "+f"(acc[3])
                    : "r"(a0), "r"(a1), "r"(a2), "r"(a3), "r"(b0), "r"(b1));
                asm volatile(
                    "mma.sync.aligned.m16n8k16.row.col.f32.bf16.bf16.f32 "
                    "{%0,%1,%2,%3}, {%4,%5,%6,%7}, {%8,%9}, {%0,%1,%2,%3};"
                    : "+f"(acc[4]), "+f"(acc[5]), "+f"(acc[6]), "+f"(acc[7])
                    : "r"(a0), "r"(a1), "r"(a2), "r"(a3), "r"(b2), "r"(b3));
            }
        }

        // ---- epilogue: fragments -> g_pr ----
        {
            const int m0 = lane >> 2;
            const int nq = (lane & 3) * 2;
#pragma unroll
            for (int tt = 0; tt < 2; tt++) {
                int b = (ntp * 2 + tt) * 8 + nq;
                int j = jg * 16 + m0;
                __stcg((float2*)&g_pr[pp][gate][kg][j][b],
                       make_float2(acc[tt * 4 + 0], acc[tt * 4 + 1]));
                __stcg((float2*)&g_pr[pp][gate][kg][j + 8][b],
                       make_float2(acc[tt * 4 + 2], acc[tt * 4 + 3]));
            }
        }
        __syncthreads();
        if (tid == 0) {
            __threadfence();
            atomicExch(&g_fA[cta], baseA + (unsigned)n + 1u);
        }

        // ---- wait: 4 kg-peers' partials ----
        if (warp == 0 && lane < 4) {
            volatile unsigned* f = &g_fA[jg * 4 + lane];
            const unsigned tgt = baseA + (unsigned)n + 1u;
            while ((int)(*f - tgt) < 0) { }
        }
        __syncthreads();

        // ---- phase B: reduce + activations + highway combine + ring write ----
        {
            float sH = __ldcg(&g_pr[pp][0][0][jB][bB]) + __ldcg(&g_pr[pp][0][1][jB][bB])
                     + __ldcg(&g_pr[pp][0][2][jB][bB]) + __ldcg(&g_pr[pp][0][3][jB][bB]);
            float sC = __ldcg(&g_pr[pp][1][0][jB][bB]) + __ldcg(&g_pr[pp][1][1][jB][bB])
                     + __ldcg(&g_pr[pp][1][2][jB][bB]) + __ldcg(&g_pr[pp][1][3][jB][bB]);
            sH += bHr[l];
            sC += bCr[l];
            if (l == 0) { sH += xh; sC += xc; }
            float hl = 1.0f - 2.0f / (1.0f + __expf(2.0f * sH));   // tanh
            float tl = 1.0f / (1.0f + __expf(-sC));                // sigmoid
            float hn = fmaf(tl, hl - hold, hold);
            hold = hn;
            __nv_bfloat16 hib = __float2bfloat16_rn(hn);
            float lo = hn - __bfloat162float(hib);
            __nv_bfloat16 lob = __float2bfloat16_rn(lo);
            asm volatile("st.global.cg.u16 [%0], %1;"
                         :: "l"(&g_hb[ns][0][jB][bB]),
                            "h"(*(unsigned short*)&hib) : "memory");
            asm volatile("st.global.cg.u16 [%0], %1;"
                         :: "l"(&g_hb[ns][1][jB][bB]),
                            "h"(*(unsigned short*)&lob) : "memory");
            if (l == L_SZ - 1) {
                size_t o = (size_t)t * (B_SZ * 2 * H_SZ) + (size_t)bB * (2 * H_SZ)
                         + (size_t)pass * H_SZ + jB;
                out[o] = hn;
                if (t == T_LEN - 1) {
                    out[(size_t)T_LEN * (B_SZ * 2 * H_SZ) + (size_t)bB * (2 * H_SZ)
                        + (size_t)pass * H_SZ + jB] = hn;
                }
            }
        }
        __syncthreads();
        if (tid == 0) {
            __threadfence();
            atomicExch(&g_fB[cta], baseB + (unsigned)n + 1u);
        }
    }
}

extern "C" void kernel_launch(void* const* d_in, const int* in_sizes, int n_in,
                              void* d_out, int out_size)
{
    const float* x   = (const float*)d_in[0];
    const float* WHw = (const float*)d_in[1];
    const float* WHb = (const float*)d_in[2];
    const float* WCw = (const float*)d_in[3];
    const float* WCb = (const float*)d_in[4];
    const float* RHw = (const float*)d_in[5];
    const float* RHb = (const float*)d_in[6];
    const float* RCw = (const float*)d_in[7];
    const float* RCb = (const float*)d_in[8];
    float* out = (float*)d_out;

    init_kernel<<<32, 256>>>();
    split_kernel<<<10240, 256>>>(RHw, RCw);
    dim3 pg(256, 8);
    proj_kernel<<<pg, NTHR>>>(x, WHw, WHb, 0);
    proj_kernel<<<pg, NTHR>>>(x, WCw, WCb, 1);
    rhn_seq_kernel<<<NCTA, NTHR>>>(RHb, RCb, out);
}